// round 8
// baseline (speedup 1.0000x reference)
#include <cuda_runtime.h>
#include <cstdint>

#define PP 64
#define TT 8192
#define KK 8
#define NN 8189            // N = T - HIST - 1
#define NPAD 8192          // padded event count
#define NPAST 64
#define NSTATE 4096        // NPAST * NPAST
#define HIST_U32 8192      // 32768 u8 counts packed into u32 (32 KB)
#define NTILE 256          // phase-A jobs (32 rows each)
#define NPREP 256          // phase-B jobs (4 per column)
#define NPAIR (PP*(PP-1))  // 4032

// scratch (no cudaMalloc allowed)
__device__ uint16_t g_a[PP][NPAD];       // (yp*128 + (yf>>2)) | ((yf&3)<<14)
__device__ uint16_t g_b[PP][NPAD];       // xp*2
__device__ float    g_hy[PP];            // H(y | y_past) per target column
__device__ float    g_pmn[NTILE][PP];    // per-tile per-column min partials
__device__ float    g_pmx[NTILE][PP];    // per-tile per-column max partials
__device__ unsigned g_cy[PP][NPAST*KK];  // per-column (yp,yf) counts
__device__ int      g_barA = 0;
__device__ int      g_barB = 0;
__device__ int      g_done = 0;
__device__ int      g_colcnt[PP] = {};

// c*log2(c) for c>=2; exact constants for the dominant small counts (keeps
// MUFU traffic low -- MUFU is ~70% busy in the pair phase).
__device__ __forceinline__ float lt_small(unsigned c)
{
    if (c < 5u)
        return (c == 2u) ? 2.0f : ((c == 3u) ? 4.754887461662292f : 8.0f);
    float f = (float)c;
    return f * __log2f(f);
}

__device__ __forceinline__ void bump2u8(unsigned* h, unsigned sum)
{
    // low half: word = sum & 0x3fff, shift = ((sum>>14)&3)*8 = (sum>>11)&0x18
    atomicAdd(&h[sum & 0x3fffu],         1u << ((sum >> 11) & 0x18u));
    atomicAdd(&h[(sum >> 16) & 0x3fffu], 1u << ((sum >> 27) & 0x18u));
}

__device__ __forceinline__ float ent8(unsigned lo, unsigned hi)
{
    unsigned ps  = lo + hi;                       // byte-wise, carry-free
    unsigned tot = __dp4a(ps, 0x01010101u, 0u);
    float a2 = 0.0f;
    if (tot >= 2) {
        a2 = lt_small(tot);
        #pragma unroll
        for (int k = 0; k < 4; k++) {
            unsigned c0 = (lo >> (k * 8)) & 0xffu;
            if (c0 >= 2) a2 -= lt_small(c0);
            unsigned c1 = (hi >> (k * 8)) & 0xffu;
            if (c1 >= 2) a2 -= lt_small(c1);
        }
    }
    return a2;
}

// ---------------------------------------------------------------------------
// Persistent monolithic kernel. G = gridDim.x blocks, all co-resident
// (G computed host-side from the occupancy API), so spin barriers are safe.
// ---------------------------------------------------------------------------
__global__ __launch_bounds__(512, 4) void mono_kernel(
    const float* __restrict__ ts, float* __restrict__ out, int G)
{
    __shared__ unsigned s_hist[HIST_U32];   // 32 KB, overlaid per phase
    __shared__ float    s_red[16];
    __shared__ float    s_par[2];
    __shared__ int      s_flat;
    __shared__ int      s_last;

    const int bid  = blockIdx.x;
    const int tid  = threadIdx.x;
    const int lane = tid & 31;
    const int wid  = tid >> 5;

    // ===================== Phase A: min/max partials + zero g_cy ==========
    for (int j = bid; j < NTILE; j += G) {
        float* s_mnA = (float*)s_hist;            // 512 floats
        float* s_mxA = (float*)s_hist + 512;
        const int col  = tid & 63;
        const int slot = tid >> 6;                // 0..7
        const int base = j * 2048;                // 32 rows * 64 cols

        float mn =  3.402823466e38f;
        float mx = -3.402823466e38f;
        #pragma unroll
        for (int k = 0; k < 4; k++) {
            float v = ts[base + tid + k * 512];   // coalesced; col fixed per thread
            mn = fminf(mn, v);
            mx = fmaxf(mx, v);
        }
        s_mnA[slot * PP + col] = mn;
        s_mxA[slot * PP + col] = mx;
        __syncthreads();
        if (tid < PP) {
            float m = s_mnA[tid], M = s_mxA[tid];
            #pragma unroll
            for (int i = 1; i < 8; i++) {
                m = fminf(m, s_mnA[i * PP + tid]);
                M = fmaxf(M, s_mxA[i * PP + tid]);
            }
            g_pmn[j][tid] = m;
            g_pmx[j][tid] = M;
        }
        __syncthreads();
    }
    for (int i = bid * 512 + tid; i < PP * NPAST * KK; i += G * 512)
        ((unsigned*)g_cy)[i] = 0u;

    // ---- barrier A ----
    __syncthreads();
    if (tid == 0) {
        __threadfence();
        atomicAdd(&g_barA, 1);
        while (*(volatile int*)&g_barA < G) __nanosleep(64);
        __threadfence();
    }
    __syncthreads();

    // ===================== Phase B: prep, 4 jobs per column ================
    for (int j = bid; j < NPREP; j += G) {
        const int p    = j >> 2;
        const int q    = j & 3;
        const int base = q * 2048;
        uint8_t*  s_dig = (uint8_t*)s_hist;            // 2051 bytes
        unsigned* s_cyB = s_hist + 768;                // 512 words @ 3 KB offset

        // min/max from the 256 partials
        float mn =  3.402823466e38f;
        float mx = -3.402823466e38f;
        if (tid < NTILE) {
            mn = g_pmn[tid][p];
            mx = g_pmx[tid][p];
        }
        #pragma unroll
        for (int o = 16; o; o >>= 1) {
            mn = fminf(mn, __shfl_xor_sync(0xffffffffu, mn, o));
            mx = fmaxf(mx, __shfl_xor_sync(0xffffffffu, mx, o));
        }
        if (lane == 0 && wid < 8) { s_red[wid] = mn; s_red[8 + wid] = mx; }
        if (tid < 512) s_cyB[tid] = 0u;
        __syncthreads();
        if (tid == 0) {
            float m = s_red[0], M = s_red[8];
            #pragma unroll
            for (int i = 1; i < 8; i++) { m = fminf(m, s_red[i]); M = fmaxf(M, s_red[8 + i]); }
            float rng = __fsub_rn(M, m);
            s_par[0] = m;
            s_par[1] = __fadd_rn(rng, 1e-8f);
            s_flat   = (rng < 1e-8f);
        }
        __syncthreads();

        const float xmin = s_par[0];
        const float den  = s_par[1];
        const int   flat = s_flat;

        // digitize slice [base, base+2051) of column p (strided reads, L2-hot)
        for (int k = tid; k < 2051; k += 512) {
            int t = base + k;
            if (t < TT) {
                float norm = __fdiv_rn(__fsub_rn(ts[t * PP + p], xmin), den);
                int b = min(max((int)__fmul_rn(norm, 7.0f), 0), KK - 1);
                s_dig[k] = flat ? (uint8_t)0 : (uint8_t)b;
            }
        }
        __syncthreads();

        // events i in [base, base+2048): packed streams + local cy histogram
        for (int k = tid; k < 2048; k += 512) {
            int i = base + k;
            if (i < NN) {
                unsigned d1 = s_dig[k + 1], d2 = s_dig[k + 2], d3 = s_dig[k + 3];
                unsigned yp = d2 + 8u * d1;
                g_a[p][i] = (uint16_t)((yp * 128u + (d3 >> 2)) | ((d3 & 3u) << 14));
                g_b[p][i] = (uint16_t)(yp * 2u);
                atomicAdd(&s_cyB[yp * KK + d3], 1u);
            } else {
                g_a[p][i] = 0;
                g_b[p][i] = 0;
            }
        }
        __syncthreads();

        // merge into global cy
        if (tid < 512) {
            unsigned c = s_cyB[tid];
            if (c) atomicAdd(&g_cy[p][tid], c);
        }
        __threadfence();
        __syncthreads();
        if (tid == 0) s_last = (atomicAdd(&g_colcnt[p], 1) == 3);
        __syncthreads();

        if (s_last) {                      // last quarter: compute H(y|yp)
            if (tid == 0) __threadfence(); // acquire other quarters' merges
            __syncthreads();
            float* s_term = (float*)s_hist;
            if (tid < NPAST) {
                unsigned tot = 0;
                float acc = 0.0f;
                #pragma unroll
                for (int y = 0; y < KK; y++) {
                    unsigned c = __ldcg(&g_cy[p][tid * KK + y]);  // L1-bypass
                    tot += c;
                    if (c >= 2) acc -= (float)c * __log2f((float)c);
                }
                if (tot >= 2) acc += (float)tot * __log2f((float)tot);
                else          acc  = 0.0f;
                s_term[tid] = acc;
            }
            __syncthreads();
            if (tid == 0) {
                float h = 0.0f;
                for (int i = 0; i < NPAST; i++) h += s_term[i];
                g_hy[p] = h / (float)NN;
                out[p * 65] = 0.0f;        // diagonal output element
            }
        }
        __syncthreads();
    }

    // ---- barrier B ----
    __syncthreads();
    if (tid == 0) {
        __threadfence();
        atomicAdd(&g_barB, 1);
        while (*(volatile int*)&g_barB < G) __nanosleep(64);
        __threadfence();
    }
    __syncthreads();

    // ===================== Phase D: pair jobs ==============================
    for (int job = bid; job < NPAIR; job += G) {
        const int s = job / 63;
        const int r = job - s * 63;
        const int t = r + (r >= s ? 1 : 0);

        // zero histogram
        uint4* h4 = (uint4*)s_hist;
        #pragma unroll
        for (int i = tid; i < HIST_U32 / 4; i += 512)
            h4[i] = make_uint4(0u, 0u, 0u, 0u);
        __syncthreads();

        // build joint histogram: 16 events per thread
        const uint4* __restrict__ A = (const uint4*)&g_a[t][0];
        const uint4* __restrict__ B = (const uint4*)&g_b[s][0];
        #pragma unroll
        for (int c = 0; c < 2; c++) {
            int u = tid + c * 512;               // uint4 index, 0..1023
            uint4 va = A[u];
            uint4 vb = B[u];
            if (u != 1023) {                     // 8 valid events
                bump2u8(s_hist, va.x + vb.x);
                bump2u8(s_hist, va.y + vb.y);
                bump2u8(s_hist, va.z + vb.z);
                bump2u8(s_hist, va.w + vb.w);
            } else {                             // events 8184..8188 valid (5)
                bump2u8(s_hist, va.x + vb.x);
                bump2u8(s_hist, va.y + vb.y);
                unsigned sum = va.z + vb.z;      // event 8188 = low half only
                atomicAdd(&s_hist[sum & 0x3fffu], 1u << ((sum >> 11) & 0x18u));
            }
        }
        __syncthreads();

        // entropy sweep: one uint4 = 2 states
        float acc = 0.0f;
        #pragma unroll
        for (int qq = tid; qq < NSTATE / 2; qq += 512) {
            uint4 v = h4[qq];
            if (v.x | v.y) acc += ent8(v.x, v.y);
            if (v.z | v.w) acc += ent8(v.z, v.w);
        }
        __syncthreads();                         // hist reads done before reuse

        // block reduce (16 warps)
        #pragma unroll
        for (int o = 16; o; o >>= 1)
            acc += __shfl_xor_sync(0xffffffffu, acc, o);
        float* sr = (float*)s_hist;
        if (lane == 0) sr[wid] = acc;
        __syncthreads();
        if (tid == 0) {
            float tt = 0.0f;
            #pragma unroll
            for (int w = 0; w < 16; w++) tt += sr[w];
            float h_ypxp = tt / (float)NN;
            out[s * 64 + t] = fmaxf(0.0f, __ldcg(&g_hy[t]) - h_ypxp);
        }
        __syncthreads();                         // sr reads done before next zero
    }

    // ===================== replay reset ====================================
    __syncthreads();
    if (tid == 0) {
        if (atomicAdd(&g_done, 1) == G - 1) {    // globally last block
            g_barA = 0;
            g_barB = 0;
            g_done = 0;
            for (int p = 0; p < PP; p++) g_colcnt[p] = 0;
            __threadfence();
        }
    }
}

// ---------------------------------------------------------------------------
extern "C" void kernel_launch(void* const* d_in, const int* in_sizes, int n_in,
                              void* d_out, int out_size)
{
    const float* ts = (const float*)d_in[0];
    float* out = (float*)d_out;

    // deterministic, allocation-free, capture-safe host queries
    int dev = 0, nsm = 0, mab = 0;
    cudaGetDevice(&dev);
    cudaDeviceGetAttribute(&nsm, cudaDevAttrMultiProcessorCount, dev);
    cudaOccupancyMaxActiveBlocksPerMultiprocessor(&mab, mono_kernel, 512, 0);
    if (mab < 1) mab = 1;
    int G = nsm * mab;                   // all G blocks co-resident by construction
    if (G > NPAIR) G = NPAIR;

    mono_kernel<<<G, 512>>>(ts, out, G);
}

// round 9
// speedup vs baseline: 1.3354x; 1.3354x over previous
#include <cuda_runtime.h>
#include <cstdint>

#define PP 64
#define TT 8192
#define KK 8
#define NN 8189            // N = T - HIST - 1
#define NPAD 8192          // padded event count
#define NPAST 64
#define NSTATE 4096        // NPAST * NPAST
#define HIST_U32 8192      // 32768 u8 counts packed into u32 (32 KB)
#define NPAIR (PP*(PP-1))  // 4032

// scratch (no cudaMalloc allowed)
__device__ uint16_t g_a[PP][NPAD];   // (yp*128 + (yf>>2)) | ((yf&3)<<14)
__device__ uint16_t g_b[PP][NPAD];   // xp*2
__device__ float    g_hy[PP];        // H(y | y_past) per target column
__device__ int      g_flag[PP];      // column-ready flags
__device__ int      g_done = 0;      // retirement counter (replay reset)

__device__ __forceinline__ void bump2u8(unsigned* h, unsigned sum)
{
    // u8 hist: bin byte-addr = bin; word = bin>>2; shift = (bin&3)*8
    unsigned i0 = sum & 0xffffu;
    unsigned i1 = sum >> 16;
    atomicAdd(&h[i0 >> 2], 1u << ((i0 & 3u) << 3));
    atomicAdd(&h[i1 >> 2], 1u << ((i1 & 3u) << 3));
}

// ---------------------------------------------------------------------------
// ONE kernel. Blocks 0..63: prep column bid, then set g_flag[bid].
// Blocks 64..4095: pair job; zero hist, spin on 2 flags, run R3 pair body.
// First wave (592 blocks) contains all prep blocks -> no deadlock.
// ---------------------------------------------------------------------------
__global__ __launch_bounds__(512, 4) void fused_kernel(
    const float* __restrict__ ts, float* __restrict__ out)
{
    __shared__ unsigned s_hist[HIST_U32];   // 32 KB, overlaid per role
    __shared__ float    s_par[2];
    __shared__ int      s_flat;

    const int bid  = blockIdx.x;
    const int tid  = threadIdx.x;
    const int lane = tid & 31;
    const int wid  = tid >> 5;

    if (bid < PP) {
        // ==================== PREP for column p = bid ======================
        const int p = bid;
        uint8_t*  s_dig = (uint8_t*)s_hist;          // bytes [0, 8192)
        unsigned* s_cy  = s_hist + 2048;             // words [2048, 2560)
        float*    s_red = (float*)(s_hist + 2560);   // scratch

        // pass 1: strided min/max (values re-read from L2 in pass 2)
        float mn =  3.402823466e38f;
        float mx = -3.402823466e38f;
        #pragma unroll
        for (int k = 0; k < 16; k++) {
            float v = ts[(tid + 512 * k) * PP + p];
            mn = fminf(mn, v);
            mx = fmaxf(mx, v);
        }
        #pragma unroll
        for (int o = 16; o; o >>= 1) {
            mn = fminf(mn, __shfl_xor_sync(0xffffffffu, mn, o));
            mx = fmaxf(mx, __shfl_xor_sync(0xffffffffu, mx, o));
        }
        if (lane == 0) { s_red[wid] = mn; s_red[16 + wid] = mx; }
        __syncthreads();
        if (tid == 0) {
            float m = s_red[0], M = s_red[16];
            #pragma unroll
            for (int i = 1; i < 16; i++) {
                m = fminf(m, s_red[i]);
                M = fmaxf(M, s_red[16 + i]);
            }
            float rng = __fsub_rn(M, m);
            s_par[0] = m;
            s_par[1] = __fadd_rn(rng, 1e-8f);
            s_flat   = (rng < 1e-8f);
        }
        __syncthreads();

        const float xmin = s_par[0];
        const float den  = s_par[1];
        const int   flat = s_flat;

        // pass 2: digitize (L2-hot re-read; exact op-order match with JAX)
        #pragma unroll
        for (int k = 0; k < 16; k++) {
            int t = tid + 512 * k;
            float norm = __fdiv_rn(__fsub_rn(ts[t * PP + p], xmin), den);
            int b = min(max((int)__fmul_rn(norm, 7.0f), 0), KK - 1);
            s_dig[t] = flat ? (uint8_t)0 : (uint8_t)b;
        }
        s_cy[tid] = 0u;                              // 512 words, one per thread
        __syncthreads();

        // emit packed a/b streams (+zero padding) + cy histogram
        // yp[i] = d[i+2] + 8*d[i+1]; yf[i] = d[i+3]; xp identical formula.
        #pragma unroll
        for (int k = 0; k < 16; k++) {
            int i = tid + 512 * k;
            if (i < NN) {
                unsigned d1 = s_dig[i + 1], d2 = s_dig[i + 2], d3 = s_dig[i + 3];
                unsigned yp = d2 + 8u * d1;
                g_a[p][i] = (uint16_t)(yp * 512u + d3);   // u8-hist bin = yp*512+xp*8+yf
                g_b[p][i] = (uint16_t)(yp * 8u);
                atomicAdd(&s_cy[yp * KK + d3], 1u);
            } else {
                g_a[p][i] = 0;
                g_b[p][i] = 0;
            }
        }
        __syncthreads();

        // H(y|yp) = (1/N) * sum_state [tot*log2(tot) - sum_c c*log2(c)]
        float* s_term = (float*)(s_hist + 2560);
        if (tid < NPAST) {
            unsigned tot = 0;
            float acc = 0.0f;
            #pragma unroll
            for (int y = 0; y < KK; y++) {
                unsigned c = s_cy[tid * KK + y];
                tot += c;
                if (c >= 2) acc -= (float)c * __log2f((float)c);
            }
            if (tot >= 2) acc += (float)tot * __log2f((float)tot);
            else          acc  = 0.0f;   // tot in {0,1} contributes exactly 0
            s_term[tid] = acc;
        }
        __syncthreads();
        if (tid == 0) {
            float h = 0.0f;
            for (int i = 0; i < NPAST; i++) h += s_term[i];
            g_hy[p] = h / (float)NN;
            out[p * 65] = 0.0f;                      // diagonal output element
            __threadfence();                         // publish streams + hy
            atomicExch(&g_flag[p], 1);
        }
    } else {
        // ==================== PAIR job =====================================
        const int job = bid - PP;                    // 0..4031
        const int s   = job / 63;
        const int r   = job - s * 63;
        const int t   = r + (r >= s ? 1 : 0);        // skip diagonal

        // zero histogram first (useful work while producers run)
        uint4* h4 = (uint4*)s_hist;
        #pragma unroll
        for (int i = tid; i < HIST_U32 / 4; i += 512)
            h4[i] = make_uint4(0u, 0u, 0u, 0u);

        // wait for both columns to be ready
        if (tid == 0) {
            while (!(*(volatile int*)&g_flag[s] & *(volatile int*)&g_flag[t]))
                __nanosleep(128);
            __threadfence();                         // acquire
        }
        __syncthreads();

        // build joint histogram: 16 events per thread
        const uint4* __restrict__ A = (const uint4*)&g_a[t][0];
        const uint4* __restrict__ B = (const uint4*)&g_b[s][0];
        #pragma unroll
        for (int c = 0; c < 2; c++) {
            int u = tid + c * 512;                   // uint4 index, 0..1023
            uint4 va = A[u];
            uint4 vb = B[u];
            if (u != 1023) {                         // 8 valid events
                bump2u8(s_hist, va.x + vb.x);
                bump2u8(s_hist, va.y + vb.y);
                bump2u8(s_hist, va.z + vb.z);
                bump2u8(s_hist, va.w + vb.w);
            } else {                                 // events 8184..8188 (5 valid)
                bump2u8(s_hist, va.x + vb.x);
                bump2u8(s_hist, va.y + vb.y);
                unsigned sum = va.z + vb.z;          // event 8188 = low half only
                unsigned i0 = sum & 0xffffu;
                atomicAdd(&s_hist[i0 >> 2], 1u << ((i0 & 3u) << 3));
            }
        }
        __syncthreads();

        // entropy sweep: state st owns 8 u8 counts = one uint2 (R3 form)
        float acc = 0.0f;
        const uint2* h2 = (const uint2*)s_hist;
        #pragma unroll
        for (int st = tid; st < NSTATE; st += 512) {
            uint2 v = h2[st];
            if (v.x | v.y) {
                unsigned ps  = v.x + v.y;                     // byte-wise, carry-free
                unsigned tot = __dp4a(ps, 0x01010101u, 0u);   // sum of all 8 bytes
                if (tot >= 2) {
                    float a2 = (float)tot * __log2f((float)tot);
                    #pragma unroll
                    for (int k = 0; k < 4; k++) {
                        unsigned c0 = (v.x >> (k * 8)) & 0xffu;
                        if (c0 >= 2) a2 -= (float)c0 * __log2f((float)c0);
                        unsigned c1 = (v.y >> (k * 8)) & 0xffu;
                        if (c1 >= 2) a2 -= (float)c1 * __log2f((float)c1);
                    }
                    acc += a2;
                }
            }
        }
        __syncthreads();   // hist reads done before reuse as scratch

        // block reduce (16 warps)
        #pragma unroll
        for (int o = 16; o; o >>= 1)
            acc += __shfl_xor_sync(0xffffffffu, acc, o);
        float* sr = (float*)s_hist;
        if (lane == 0) sr[wid] = acc;
        __syncthreads();
        if (tid == 0) {
            float tt = 0.0f;
            #pragma unroll
            for (int w = 0; w < 16; w++) tt += sr[w];
            float h_ypxp = tt / (float)NN;
            out[s * 64 + t] = fmaxf(0.0f, __ldcg(&g_hy[t]) - h_ypxp);
        }
    }

    // ==================== replay reset =====================================
    __syncthreads();
    if (tid == 0) {
        if (atomicAdd(&g_done, 1) == (int)gridDim.x - 1) {  // globally last block
            #pragma unroll
            for (int i = 0; i < PP; i++) g_flag[i] = 0;
            g_done = 0;
            __threadfence();
        }
    }
}

// ---------------------------------------------------------------------------
extern "C" void kernel_launch(void* const* d_in, const int* in_sizes, int n_in,
                              void* d_out, int out_size)
{
    const float* ts = (const float*)d_in[0];
    float* out = (float*)d_out;

    fused_kernel<<<PP + NPAIR, 512>>>(ts, out);
}

// round 10
// speedup vs baseline: 1.4868x; 1.1133x over previous
#include <cuda_runtime.h>
#include <cstdint>

#define PP 64
#define TT 8192
#define KK 8
#define NN 8189            // N = T - HIST - 1
#define NPAD 8192          // padded event count (16B-aligned rows)
#define NPAST 64
#define NSTATE 4096        // NPAST * NPAST
#define HIST_U32 8192      // 32768 u8 counts packed into u32 (32 KB)
#define MMB 256            // tiles / minmax partial blocks

// scratch (no cudaMalloc allowed)
__device__ float    g_cm[PP][TT];        // column-major copy of input
__device__ uint16_t g_a[PP][NPAD];       // (yp*128 + (yf>>2)) | ((yf&3)<<14)
__device__ uint16_t g_b[PP][NPAD];       // xp*2
__device__ float    g_hy[PP];            // H(y | y_past) per target column
__device__ float    g_pmn[MMB][PP];      // per-tile per-column min partials
__device__ float    g_pmx[MMB][PP];      // per-tile per-column max partials
__device__ unsigned g_cy[PP][NPAST*KK];  // per-column (yp,yf) counts
__device__ int      g_colcnt[PP] = {};   // prep slice-finish counters

// ---------------------------------------------------------------------------
// K0: fused transpose + min/max partials (R6-measured 4.8us). Also zeroes
// g_cy and resets g_colcnt so the launch sequence is replay-idempotent.
// ---------------------------------------------------------------------------
__global__ __launch_bounds__(512) void tmm_kernel(const float* __restrict__ ts)
{
    __shared__ float s_tile[32][65];
    __shared__ float s_mn[8 * PP];
    __shared__ float s_mx[8 * PP];

    const int tid  = threadIdx.x;
    const int col  = tid & 63;
    const int slot = tid >> 6;                 // 0..7
    const int r0   = blockIdx.x * 32;
    const int base = blockIdx.x * 2048;        // 32 rows * 64 cols

    float mn =  3.402823466e38f;
    float mx = -3.402823466e38f;
    #pragma unroll
    for (int k = 0; k < 4; k++) {
        int i = tid + k * 512;                 // element within tile
        float v = ts[base + i];                // coalesced read
        s_tile[i >> 6][i & 63] = v;            // row = i>>6, col = i&63
        mn = fminf(mn, v);                     // this thread's elems are column (tid&63)
        mx = fmaxf(mx, v);
    }
    s_mn[slot * PP + col] = mn;
    s_mx[slot * PP + col] = mx;
    __syncthreads();

    #pragma unroll
    for (int k = 0; k < 4; k++) {
        int i = tid + k * 512;                 // 0..2047
        int c = i >> 5;                        // column 0..63
        int r = i & 31;                        // row within tile
        g_cm[c][r0 + r] = s_tile[r][c];        // coalesced, conflict-free
    }

    if (tid < PP) {
        float m = s_mn[tid], M = s_mx[tid];
        #pragma unroll
        for (int i = 1; i < 8; i++) {
            m = fminf(m, s_mn[i * PP + tid]);
            M = fmaxf(M, s_mx[i * PP + tid]);
        }
        g_pmn[blockIdx.x][tid] = m;
        g_pmx[blockIdx.x][tid] = M;
    }

    // zero g_cy (one word per thread for bids 0..63) + reset colcnt
    {
        int i = blockIdx.x * 512 + tid;
        if (i < PP * NPAST * KK) ((unsigned*)g_cy)[i] = 0u;
    }
    if (blockIdx.x == 0 && tid < PP) g_colcnt[tid] = 0;
}

// ---------------------------------------------------------------------------
// K1: prep, 256 blocks = 4 slices per column. Min/max from partials; digitize
// slice from contiguous g_cm; emit packed a/b stream slice; merge slice cy
// into g_cy; the LAST slice-finisher per column computes H(y|yp).
// ---------------------------------------------------------------------------
__global__ __launch_bounds__(512) void prep_kernel(float* __restrict__ out)
{
    __shared__ uint8_t  s_dig[2051 + 13];   // slice digits (+pad)
    __shared__ unsigned s_cy[NPAST * KK];   // 2 KB
    __shared__ float    s_red[16];
    __shared__ float    s_par[2];
    __shared__ int      s_flat;
    __shared__ int      s_last;
    __shared__ float    s_term[NPAST];

    const int bid  = blockIdx.x;
    const int p    = bid >> 2;
    const int q    = bid & 3;
    const int base = q * 2048;
    const int tid  = threadIdx.x;
    const int lane = tid & 31;
    const int wid  = tid >> 5;

    // ---- min/max from the 256 partials for column p ----
    float mn =  3.402823466e38f;
    float mx = -3.402823466e38f;
    if (tid < MMB) {
        mn = g_pmn[tid][p];
        mx = g_pmx[tid][p];
    }
    #pragma unroll
    for (int o = 16; o; o >>= 1) {
        mn = fminf(mn, __shfl_xor_sync(0xffffffffu, mn, o));
        mx = fmaxf(mx, __shfl_xor_sync(0xffffffffu, mx, o));
    }
    if (lane == 0 && wid < 8) { s_red[wid] = mn; s_red[8 + wid] = mx; }
    if (tid < NPAST * KK) s_cy[tid] = 0u;
    __syncthreads();
    if (tid == 0) {
        float m = s_red[0], M = s_red[8];
        #pragma unroll
        for (int i = 1; i < 8; i++) { m = fminf(m, s_red[i]); M = fmaxf(M, s_red[8 + i]); }
        float rng = __fsub_rn(M, m);
        s_par[0] = m;
        s_par[1] = __fadd_rn(rng, 1e-8f);
        s_flat   = (rng < 1e-8f);
    }
    __syncthreads();

    const float xmin = s_par[0];
    const float den  = s_par[1];
    const int   flat = s_flat;

    // ---- digitize slice [base, base+2051) (exact op-order match with JAX) ----
    for (int k = tid; k < 2051; k += 512) {
        int t = base + k;
        if (t < TT) {
            float norm = __fdiv_rn(__fsub_rn(g_cm[p][t], xmin), den);
            int b = min(max((int)__fmul_rn(norm, 7.0f), 0), KK - 1);
            s_dig[k] = flat ? (uint8_t)0 : (uint8_t)b;
        }
    }
    __syncthreads();

    // ---- packed a/b stream slice (+zero padding) + slice cy histogram ----
    #pragma unroll
    for (int c = 0; c < 4; c++) {
        int k = tid + c * 512;
        int i = base + k;
        if (i < NN) {
            unsigned d1 = s_dig[k + 1], d2 = s_dig[k + 2], d3 = s_dig[k + 3];
            unsigned yp = d2 + 8u * d1;
            g_a[p][i] = (uint16_t)((yp * 128u + (d3 >> 2)) | ((d3 & 3u) << 14));
            g_b[p][i] = (uint16_t)(yp * 2u);
            atomicAdd(&s_cy[yp * KK + d3], 1u);
        } else {
            g_a[p][i] = 0;
            g_b[p][i] = 0;
        }
    }
    __syncthreads();

    // ---- merge slice cy into global, then last slice computes H(y|yp) ----
    if (tid < NPAST * KK) {
        unsigned c = s_cy[tid];
        if (c) atomicAdd(&g_cy[p][tid], c);
    }
    __threadfence();
    __syncthreads();
    if (tid == 0) s_last = (atomicAdd(&g_colcnt[p], 1) == 3);
    __syncthreads();

    if (s_last) {
        if (tid == 0) __threadfence();     // acquire other slices' merges
        __syncthreads();
        if (tid < NPAST) {
            unsigned tot = 0;
            float acc = 0.0f;
            #pragma unroll
            for (int y = 0; y < KK; y++) {
                unsigned c = __ldcg(&g_cy[p][tid * KK + y]);   // bypass stale L1
                tot += c;
                if (c >= 2) acc -= (float)c * __log2f((float)c);
            }
            if (tot >= 2) acc += (float)tot * __log2f((float)tot);
            else          acc  = 0.0f;     // tot in {0,1} contributes exactly 0
            s_term[tid] = acc;
        }
        __syncthreads();
        if (tid == 0) {
            float h = 0.0f;
            for (int i = 0; i < NPAST; i++) h += s_term[i];
            g_hy[p] = h / (float)NN;
        }
    }
}

// ---------------------------------------------------------------------------
// K2: pair kernel — BYTE-IDENTICAL to the R3 measured-best version.
// One block (512 threads) per (source s, target t) pair; 32 KB u8 histogram;
// diagonal blocks early-out; entropy sweep on MUFU.
// ---------------------------------------------------------------------------
__device__ __forceinline__ void bump2u8(unsigned* h, unsigned sum)
{
    // low half: word = sum & 0x3fff, shift = ((sum>>14)&3)*8 = (sum>>11)&0x18
    atomicAdd(&h[sum & 0x3fffu],         1u << ((sum >> 11) & 0x18u));
    atomicAdd(&h[(sum >> 16) & 0x3fffu], 1u << ((sum >> 27) & 0x18u));
}

__global__ __launch_bounds__(512) void pair_kernel(float* __restrict__ out)
{
    __shared__ unsigned s_hist[HIST_U32];   // 32 KB

    const int pair = blockIdx.x;
    const int s = pair >> 6;
    const int t = pair & 63;
    const int tid = threadIdx.x;

    if (s == t) {                            // diagonal: result is 0 by spec
        if (tid == 0) out[pair] = 0.0f;
        return;
    }

    // zero histogram: 4 uint4 per thread
    uint4* h4 = (uint4*)s_hist;
    #pragma unroll
    for (int i = tid; i < HIST_U32 / 4; i += 512)
        h4[i] = make_uint4(0u, 0u, 0u, 0u);
    __syncthreads();

    // build joint histogram: 2 uint4-pairs per thread (16 events)
    const uint4* __restrict__ A = (const uint4*)&g_a[t][0];
    const uint4* __restrict__ B = (const uint4*)&g_b[s][0];
    #pragma unroll
    for (int c = 0; c < 2; c++) {
        int u = tid + c * 512;               // uint4 index, 0..1023
        uint4 va = A[u];
        uint4 vb = B[u];
        if (u != 1023) {                     // 8 valid events
            bump2u8(s_hist, va.x + vb.x);
            bump2u8(s_hist, va.y + vb.y);
            bump2u8(s_hist, va.z + vb.z);
            bump2u8(s_hist, va.w + vb.w);
        } else {                             // events 8184..8188 valid (5)
            bump2u8(s_hist, va.x + vb.x);
            bump2u8(s_hist, va.y + vb.y);
            unsigned sum = va.z + vb.z;      // event 8188 = low half only
            atomicAdd(&s_hist[sum & 0x3fffu], 1u << ((sum >> 11) & 0x18u));
        }
    }
    __syncthreads();

    // entropy sweep: state st owns 8 u8 counts = one uint2
    float acc = 0.0f;
    const uint2* h2 = (const uint2*)s_hist;
    #pragma unroll
    for (int st = tid; st < NSTATE; st += 512) {
        uint2 v = h2[st];
        if (v.x | v.y) {
            unsigned ps  = v.x + v.y;                     // byte-wise, carry-free
            unsigned tot = __dp4a(ps, 0x01010101u, 0u);   // sum of all 8 bytes
            if (tot >= 2) {
                float a2 = (float)tot * __log2f((float)tot);
                #pragma unroll
                for (int k = 0; k < 4; k++) {
                    unsigned c0 = (v.x >> (k * 8)) & 0xffu;
                    if (c0 >= 2) a2 -= (float)c0 * __log2f((float)c0);
                    unsigned c1 = (v.y >> (k * 8)) & 0xffu;
                    if (c1 >= 2) a2 -= (float)c1 * __log2f((float)c1);
                }
                acc += a2;
            }
        }
    }
    __syncthreads();   // everyone done reading hist before reuse as scratch

    // block reduce (16 warps)
    #pragma unroll
    for (int o = 16; o; o >>= 1)
        acc += __shfl_xor_sync(0xffffffffu, acc, o);
    float* sr = (float*)s_hist;
    if ((tid & 31) == 0) sr[tid >> 5] = acc;
    __syncthreads();
    if (tid == 0) {
        float tt = 0.0f;
        #pragma unroll
        for (int w = 0; w < 16; w++) tt += sr[w];
        float h_ypxp = tt / (float)NN;
        out[pair] = fmaxf(0.0f, g_hy[t] - h_ypxp);   // out[s*64 + t]
    }
}

// ---------------------------------------------------------------------------
extern "C" void kernel_launch(void* const* d_in, const int* in_sizes, int n_in,
                              void* d_out, int out_size)
{
    const float* ts = (const float*)d_in[0];
    float* out = (float*)d_out;

    tmm_kernel<<<MMB, 512>>>(ts);
    prep_kernel<<<MMB, 512>>>(out);
    pair_kernel<<<PP * PP, 512>>>(out);
}